// round 2
// baseline (speedup 1.0000x reference)
#include <cuda_runtime.h>
#include <math.h>

// DuplicateRemovalLayer: x (B,16,3) fp32 -> out (B,16,3) fp32.
// Groups [0:6),[6:9),[9:12),[12:15): object j zeroed iff ANY later object i
// in its group has dR(i,j) < 0.05; inactive objects (pt<=0) use eta=phi=1e6
// sentinels (so two inactive objects ARE mutual duplicates). Index 15 passthrough.
//
// dphi wrap done with rintf range reduction (sign-free, enters as dphi^2 only),
// threshold compared on dr^2. Staged through padded shared memory (stride 49,
// conflict-free compute access), fully-unrolled coalesced float4 IO.

#define THREADS 128
#define BPB     128            // batches per block
#define FPB     48             // floats per batch (16*3)
#define F4PB    12             // float4 per batch
#define PAD     49             // padded floats per batch in smem

__device__ __forceinline__ bool is_dup(float ei, float pi_, float ej, float pj) {
    const float TWOPI  = 6.28318530717958647692f;
    const float INV2PI = 0.15915494309189533577f;
    float deta = ei - ej;
    float d    = pi_ - pj;
    float dphi = fmaf(-TWOPI, rintf(d * INV2PI), d);   // wrapped to [-pi, pi]
    return fmaf(deta, deta, dphi * dphi) < 0.0025f;    // dr^2 < 0.05^2
}

template <int N>
__device__ __forceinline__ void remove_group(const float* E, const float* P,
                                             unsigned& keep, int s0) {
    #pragma unroll
    for (int i = 1; i < N; i++) {
        #pragma unroll
        for (int j = 0; j < i; j++) {
            if (is_dup(E[s0 + i], P[s0 + i], E[s0 + j], P[s0 + j]))
                keep &= ~(1u << (s0 + j));
        }
    }
}

__global__ __launch_bounds__(THREADS, 8)
void dup_removal_kernel(const float* __restrict__ in, float* __restrict__ out, int B) {
    __shared__ float s[BPB * PAD];

    const int batch0 = blockIdx.x * BPB;
    const int tid = threadIdx.x;
    const long long fbase = (long long)batch0 * FPB;
    const float4* __restrict__ in4 = (const float4*)(in + fbase);
    float4* __restrict__ out4 = (float4*)(out + fbase);
    const bool full = (batch0 + BPB) <= B;

    // ---- coalesced staged load ----
    if (full) {
        float4 v[F4PB];
        #pragma unroll
        for (int k = 0; k < F4PB; k++) v[k] = in4[tid + k * THREADS];
        #pragma unroll
        for (int k = 0; k < F4PB; k++) {
            int f = tid + k * THREADS;
            int b = f / F4PB, off = (f % F4PB) * 4;
            float* dst = s + b * PAD + off;
            dst[0] = v[k].x; dst[1] = v[k].y; dst[2] = v[k].z; dst[3] = v[k].w;
        }
    } else {
        int nf4 = (B - batch0) * F4PB;
        for (int f = tid; f < nf4; f += THREADS) {
            float4 v = in4[f];
            int b = f / F4PB, off = (f % F4PB) * 4;
            float* dst = s + b * PAD + off;
            dst[0] = v.x; dst[1] = v.y; dst[2] = v.z; dst[3] = v.w;
        }
    }
    __syncthreads();

    // ---- one thread per batch: pair tests + (rare) zeroing ----
    if (batch0 + tid < B) {
        float* p = s + tid * PAD;

        float E[15], P[15];
        #pragma unroll
        for (int i = 0; i < 15; i++) {
            bool act = p[3 * i] > 0.0f;
            E[i] = act ? p[3 * i + 1] : 1000000.0f;
            P[i] = act ? p[3 * i + 2] : 1000000.0f;
        }

        unsigned keep = 0x7FFFu;
        remove_group<6>(E, P, keep, 0);    // jets
        remove_group<3>(E, P, keep, 6);    // electrons
        remove_group<3>(E, P, keep, 9);    // muons
        remove_group<3>(E, P, keep, 12);   // photons

        if (keep != 0x7FFFu) {             // duplicates are rare: branch ~never taken
            #pragma unroll
            for (int i = 0; i < 15; i++) {
                if (!(keep & (1u << i))) {
                    p[3 * i] = 0.0f; p[3 * i + 1] = 0.0f; p[3 * i + 2] = 0.0f;
                }
            }
        }
    }
    __syncthreads();

    // ---- coalesced staged store ----
    if (full) {
        #pragma unroll
        for (int k = 0; k < F4PB; k++) {
            int f = tid + k * THREADS;
            int b = f / F4PB, off = (f % F4PB) * 4;
            const float* src = s + b * PAD + off;
            out4[f] = make_float4(src[0], src[1], src[2], src[3]);
        }
    } else {
        int nf4 = (B - batch0) * F4PB;
        for (int f = tid; f < nf4; f += THREADS) {
            int b = f / F4PB, off = (f % F4PB) * 4;
            const float* src = s + b * PAD + off;
            out4[f] = make_float4(src[0], src[1], src[2], src[3]);
        }
    }
}

extern "C" void kernel_launch(void* const* d_in, const int* in_sizes, int n_in,
                              void* d_out, int out_size) {
    const float* x = (const float*)d_in[0];
    float* out = (float*)d_out;
    const int B = in_sizes[0] / FPB;
    const int grid = (B + BPB - 1) / BPB;
    dup_removal_kernel<<<grid, THREADS>>>(x, out, B);
}

// round 3
// speedup vs baseline: 1.3276x; 1.3276x over previous
#include <cuda_runtime.h>
#include <math.h>

// DuplicateRemovalLayer: x (B,16,3) fp32 -> out (B,16,3) fp32.
// Groups [0:6),[6:9),[9:12),[12:15): object j zeroed iff ANY later object i
// in its group has dR(i,j) < 0.05; inactive objects (pt<=0) use eta=phi=1e6
// sentinels (two inactive objects ARE mutual duplicates). Index 15 passthrough.
//
// All shared-memory traffic is 128-bit and conflict-free: PAD=52 floats
// (13 float4, 13 odd mod 8 -> all 8 quad-bank groups covered per phase).
// Compute phase loads the batch as 12 LDS.128, computes keep-mask in
// registers, and writes back ONLY zeros for removed objects (smem already
// holds the unmodified data). dphi via rintf range reduction; dr^2 compare.

#define THREADS 128
#define BPB     128            // batches per block
#define FPB     48             // floats per batch (16*3)
#define F4PB    12             // float4 per batch
#define PADV    13             // padded float4 per batch (odd mod 8)

__device__ __forceinline__ bool is_dup(float ei, float pi_, float ej, float pj) {
    const float TWOPI  = 6.28318530717958647692f;
    const float INV2PI = 0.15915494309189533577f;
    float deta = ei - ej;
    float d    = pi_ - pj;
    float dphi = fmaf(-TWOPI, rintf(d * INV2PI), d);   // wrapped, enters squared
    return fmaf(deta, deta, dphi * dphi) < 0.0025f;    // dr^2 < 0.05^2
}

template <int N>
__device__ __forceinline__ void remove_group(const float* E, const float* P,
                                             unsigned& keep, int s0) {
    #pragma unroll
    for (int i = 1; i < N; i++) {
        #pragma unroll
        for (int j = 0; j < i; j++) {
            if (is_dup(E[s0 + i], P[s0 + i], E[s0 + j], P[s0 + j]))
                keep &= ~(1u << (s0 + j));
        }
    }
}

__global__ __launch_bounds__(THREADS, 8)
void dup_removal_kernel(const float* __restrict__ in, float* __restrict__ out, int B) {
    __shared__ float4 s4[BPB * PADV];

    const int batch0 = blockIdx.x * BPB;
    const int tid = threadIdx.x;
    const long long fbase = (long long)batch0 * FPB;
    const float4* __restrict__ in4 = (const float4*)(in + fbase);
    float4* __restrict__ out4 = (float4*)(out + fbase);
    const bool full = (batch0 + BPB) <= B;
    const int nvalid = full ? BPB : (B - batch0);

    // ---- phase 1: coalesced LDG.128 -> padded smem (STS.128) ----
    if (full) {
        #pragma unroll
        for (int k = 0; k < F4PB; k++) {
            int f = tid + k * THREADS;
            float4 v = in4[f];
            s4[(f / F4PB) * PADV + (f % F4PB)] = v;
        }
    } else {
        int nf4 = nvalid * F4PB;
        for (int f = tid; f < nf4; f += THREADS) {
            s4[(f / F4PB) * PADV + (f % F4PB)] = in4[f];
        }
    }
    __syncthreads();

    // ---- phase 2: one thread per batch; vector gather, zeros written sparsely ----
    if (tid < nvalid) {
        float4* pb = s4 + tid * PADV;
        float p[FPB];
        #pragma unroll
        for (int k = 0; k < F4PB; k++) {            // 12 LDS.128, conflict-free
            float4 v = pb[k];
            p[4 * k] = v.x; p[4 * k + 1] = v.y; p[4 * k + 2] = v.z; p[4 * k + 3] = v.w;
        }

        float E[15], P[15];
        #pragma unroll
        for (int i = 0; i < 15; i++) {
            bool act = p[3 * i] > 0.0f;
            E[i] = act ? p[3 * i + 1] : 1000000.0f;
            P[i] = act ? p[3 * i + 2] : 1000000.0f;
        }

        unsigned keep = 0x7FFFu;
        remove_group<6>(E, P, keep, 0);    // jets
        remove_group<3>(E, P, keep, 6);    // electrons
        remove_group<3>(E, P, keep, 9);    // muons
        remove_group<3>(E, P, keep, 12);   // photons

        float* ps = (float*)pb;
        #pragma unroll
        for (int i = 0; i < 15; i++) {
            if (!(keep & (1u << i))) {               // sparse scalar zero-stores
                ps[3 * i] = 0.0f; ps[3 * i + 1] = 0.0f; ps[3 * i + 2] = 0.0f;
            }
        }
    }
    __syncthreads();

    // ---- phase 3: padded smem (LDS.128) -> coalesced STG.128 ----
    if (full) {
        #pragma unroll
        for (int k = 0; k < F4PB; k++) {
            int f = tid + k * THREADS;
            out4[f] = s4[(f / F4PB) * PADV + (f % F4PB)];
        }
    } else {
        int nf4 = nvalid * F4PB;
        for (int f = tid; f < nf4; f += THREADS) {
            out4[f] = s4[(f / F4PB) * PADV + (f % F4PB)];
        }
    }
}

extern "C" void kernel_launch(void* const* d_in, const int* in_sizes, int n_in,
                              void* d_out, int out_size) {
    const float* x = (const float*)d_in[0];
    float* out = (float*)d_out;
    const int B = in_sizes[0] / FPB;
    const int grid = (B + BPB - 1) / BPB;
    dup_removal_kernel<<<grid, THREADS>>>(x, out, B);
}

// round 4
// speedup vs baseline: 1.3831x; 1.0418x over previous
#include <cuda_runtime.h>
#include <math.h>

// DuplicateRemovalLayer: x (B,16,3) fp32 -> out (B,16,3) fp32.
// Groups [0:6),[6:9),[9:12),[12:15): object j zeroed iff ANY later object i
// in its group has dR(i,j) < 0.05; inactive objects (pt<=0) use eta=phi=1e6
// sentinels (two inactive objects ARE mutual duplicates). Index 15 passthrough.
//
// Persistent-block software pipeline: 3 padded smem buffers per block,
// cp.async.cg prefetch 2 tiles ahead (one commit_group per iteration,
// wait_group 2 retires the current tile). All smem traffic 128-bit,
// conflict-free (PADV=13, odd mod 8). Evict-first stores (__stcs).

#define THREADS 128
#define BPB     128            // batches per tile
#define FPB     48             // floats per batch
#define F4PB    12             // float4 per batch
#define PADV    13             // padded float4 per batch (odd mod 8)
#define NBUF    3
#define BUF_F4  (BPB * PADV)   // 1664 float4 per buffer
#define SMEM_BYTES (NBUF * BUF_F4 * 16)   // 79,872 B

__device__ __forceinline__ void cp_async16(float4* smem_dst, const float4* gmem_src) {
    unsigned s = (unsigned)__cvta_generic_to_shared(smem_dst);
    asm volatile("cp.async.cg.shared.global [%0], [%1], 16;" :: "r"(s), "l"(gmem_src));
}
#define CP_COMMIT() asm volatile("cp.async.commit_group;" ::: "memory")
#define CP_WAIT2()  asm volatile("cp.async.wait_group 2;" ::: "memory")

__device__ __forceinline__ bool is_dup(float ei, float pi_, float ej, float pj) {
    const float TWOPI  = 6.28318530717958647692f;
    const float INV2PI = 0.15915494309189533577f;
    float deta = ei - ej;
    float d    = pi_ - pj;
    float dphi = fmaf(-TWOPI, rintf(d * INV2PI), d);   // wrapped; enters squared
    return fmaf(deta, deta, dphi * dphi) < 0.0025f;    // dr^2 < 0.05^2
}

template <int N>
__device__ __forceinline__ void remove_group(const float* E, const float* P,
                                             unsigned& keep, int s0) {
    #pragma unroll
    for (int i = 1; i < N; i++) {
        #pragma unroll
        for (int j = 0; j < i; j++) {
            if (is_dup(E[s0 + i], P[s0 + i], E[s0 + j], P[s0 + j]))
                keep &= ~(1u << (s0 + j));
        }
    }
}

// Prefetch one tile into buf (guards OOB; callers always CP_COMMIT after).
__device__ __forceinline__ void prefetch_tile(const float4* __restrict__ in4,
                                              int tile, int ntiles, int B,
                                              float4* buf, int tid) {
    if (tile < ntiles) {
        int nvalid = min(BPB, B - tile * BPB);
        int nf4 = nvalid * F4PB;
        const float4* src = in4 + (long long)tile * (BPB * F4PB);
        #pragma unroll
        for (int k = 0; k < F4PB; k++) {
            int f = tid + k * THREADS;
            if (f < nf4) cp_async16(&buf[(f / F4PB) * PADV + (f % F4PB)], &src[f]);
        }
    }
}

__global__ __launch_bounds__(THREADS)
void dup_removal_kernel(const float* __restrict__ in, float* __restrict__ out,
                        int B, int ntiles) {
    extern __shared__ float4 s4[];
    float4* bufs[NBUF] = { s4, s4 + BUF_F4, s4 + 2 * BUF_F4 };

    const int tid = threadIdx.x;
    const int G = gridDim.x;
    const int bid = blockIdx.x;

    // Prologue: prefetch tiles bid, bid+G
    prefetch_tile((const float4*)in, bid, ntiles, B, bufs[0], tid);
    CP_COMMIT();
    prefetch_tile((const float4*)in, bid + G, ntiles, B, bufs[1], tid);
    CP_COMMIT();

    int li = 0;
    for (int tile = bid; tile < ntiles; tile += G, li++) {
        float4* cur = bufs[li % NBUF];
        // Prefetch 2 ahead (empty group still committed near tail — keeps
        // the wait_group accounting exact).
        prefetch_tile((const float4*)in, tile + 2 * G, ntiles, B,
                      bufs[(li + 2) % NBUF], tid);
        CP_COMMIT();
        CP_WAIT2();                 // current tile's group retired
        __syncthreads();

        const int nvalid = min(BPB, B - tile * BPB);

        // ---- compute: one thread per batch; sparse zero write-back ----
        if (tid < nvalid) {
            float4* pb = cur + tid * PADV;
            float p[FPB];
            #pragma unroll
            for (int k = 0; k < F4PB; k++) {        // 12 LDS.128, conflict-free
                float4 v = pb[k];
                p[4*k] = v.x; p[4*k+1] = v.y; p[4*k+2] = v.z; p[4*k+3] = v.w;
            }

            float E[15], P[15];
            #pragma unroll
            for (int i = 0; i < 15; i++) {
                bool act = p[3*i] > 0.0f;
                E[i] = act ? p[3*i+1] : 1000000.0f;
                P[i] = act ? p[3*i+2] : 1000000.0f;
            }

            unsigned keep = 0x7FFFu;
            remove_group<6>(E, P, keep, 0);
            remove_group<3>(E, P, keep, 6);
            remove_group<3>(E, P, keep, 9);
            remove_group<3>(E, P, keep, 12);

            if (keep != 0x7FFFu) {
                float* ps = (float*)pb;
                #pragma unroll
                for (int i = 0; i < 15; i++) {
                    if (!(keep & (1u << i))) {
                        ps[3*i] = 0.0f; ps[3*i+1] = 0.0f; ps[3*i+2] = 0.0f;
                    }
                }
            }
        }
        __syncthreads();

        // ---- store: padded smem -> coalesced evict-first STG.128 ----
        {
            int nf4 = nvalid * F4PB;
            float4* dst = (float4*)out + (long long)tile * (BPB * F4PB);
            #pragma unroll
            for (int k = 0; k < F4PB; k++) {
                int f = tid + k * THREADS;
                if (f < nf4)
                    __stcs(&dst[f], cur[(f / F4PB) * PADV + (f % F4PB)]);
            }
        }
        __syncthreads();   // protect cur from the next prefetch that reuses it
    }
}

extern "C" void kernel_launch(void* const* d_in, const int* in_sizes, int n_in,
                              void* d_out, int out_size) {
    const float* x = (const float*)d_in[0];
    float* out = (float*)d_out;
    const int B = in_sizes[0] / FPB;
    const int ntiles = (B + BPB - 1) / BPB;

    cudaFuncSetAttribute(dup_removal_kernel,
                         cudaFuncAttributeMaxDynamicSharedMemorySize, SMEM_BYTES);

    int dev = 0, nsm = 148;
    cudaGetDevice(&dev);
    cudaDeviceGetAttribute(&nsm, cudaDevAttrMultiProcessorCount, dev);

    int grid = 2 * nsm;                 // 2 blocks/SM (smem-limited)
    if (grid > ntiles) grid = ntiles;

    dup_removal_kernel<<<grid, THREADS, SMEM_BYTES>>>(x, out, B, ntiles);
}